// round 1
// baseline (speedup 1.0000x reference)
#include <cuda_runtime.h>

#define NB  4
#define NS  2048
#define ND  512
#define NH  8
#define NDH 64
#define NEGV -1000000.0f

// Scratch (device globals: allocation-free rule)
__device__ float g_q[NB * NH * NS * NDH];    // [B,H,S,64], pre-scaled by 1/8
__device__ float g_k[NB * NH * NS * NDH];
__device__ float g_v[NB * NH * NS * NDH];
__device__ float g_ctx[NB * NS * ND];        // [B,S,D]

// ---------------------------------------------------------------------------
// Projection GEMM: C[M=8192, N=512] = X @ W^T + bias
// MODE 0: plain row-major output. MODE 1: scatter to [B,H,S,64] with scale.
// 128x128x16 tile, 256 threads, 8x8 micro-tile.
// ---------------------------------------------------------------------------
template <int MODE>
__global__ __launch_bounds__(256) void proj_kernel(
    const float* __restrict__ X, const float* __restrict__ W,
    const float* __restrict__ bias, float* __restrict__ out, float scale)
{
    __shared__ float As[128][17];                 // natural [m][k], pad 1
    __shared__ __align__(16) float Bt[16][132];   // transposed [k][n], pad 4

    const int tid = threadIdx.x;
    const int tx  = tid & 15;
    const int ty  = tid >> 4;
    const int m0  = blockIdx.x * 128;
    const int n0  = blockIdx.y * 128;

    float acc[8][8];
#pragma unroll
    for (int i = 0; i < 8; ++i)
#pragma unroll
        for (int j = 0; j < 8; ++j) acc[i][j] = 0.0f;

    const int f4 = tid & 3;   // which float4 within the 16-wide k slab
    const int r0 = tid >> 2;  // 0..63

    for (int k0 = 0; k0 < ND; k0 += 16) {
#pragma unroll
        for (int rr = 0; rr < 2; ++rr) {
            int row = r0 + rr * 64;
            float4 a4 = *(const float4*)(X + (m0 + row) * ND + k0 + f4 * 4);
            As[row][f4 * 4 + 0] = a4.x;
            As[row][f4 * 4 + 1] = a4.y;
            As[row][f4 * 4 + 2] = a4.z;
            As[row][f4 * 4 + 3] = a4.w;
            float4 b4 = *(const float4*)(W + (n0 + row) * ND + k0 + f4 * 4);
            Bt[f4 * 4 + 0][row] = b4.x;
            Bt[f4 * 4 + 1][row] = b4.y;
            Bt[f4 * 4 + 2][row] = b4.z;
            Bt[f4 * 4 + 3][row] = b4.w;
        }
        __syncthreads();

#pragma unroll
        for (int kk = 0; kk < 16; ++kk) {
            float a[8];
#pragma unroll
            for (int i = 0; i < 8; ++i) a[i] = As[ty * 8 + i][kk];
            float4 b0 = *(const float4*)&Bt[kk][tx * 8];
            float4 b1 = *(const float4*)&Bt[kk][tx * 8 + 4];
            float bb[8] = {b0.x, b0.y, b0.z, b0.w, b1.x, b1.y, b1.z, b1.w};
#pragma unroll
            for (int i = 0; i < 8; ++i)
#pragma unroll
                for (int j = 0; j < 8; ++j)
                    acc[i][j] = fmaf(a[i], bb[j], acc[i][j]);
        }
        __syncthreads();
    }

#pragma unroll
    for (int i = 0; i < 8; ++i) {
        int m = m0 + ty * 8 + i;
        int b = m / NS, s = m % NS;  // used by MODE 1 only
#pragma unroll
        for (int j = 0; j < 8; ++j) {
            int n = n0 + tx * 8 + j;
            float v = acc[i][j] + bias[n];
            if (MODE == 1) {
                v *= scale;
                int head = n >> 6, d = n & 63;
                out[((b * NH + head) * NS + s) * NDH + d] = v;
            } else {
                out[m * ND + n] = v;
            }
        }
    }
}

// ---------------------------------------------------------------------------
// Flash attention (fp32 SIMT). One CTA = one (b,h) pair x 64 query rows.
// 64x64 score tiles, online softmax, key tiles beyond masked[b] skipped.
// Thread (ty,tx) owns rows {4ty..4ty+3} x cols {tx, tx+16, tx+32, tx+48}.
// ---------------------------------------------------------------------------
__global__ __launch_bounds__(256) void attn_kernel(
    const float* __restrict__ q, const float* __restrict__ k,
    const float* __restrict__ v, float* __restrict__ ctx,
    const void* __restrict__ masked_raw)
{
    extern __shared__ float sm[];
    float* Qt = sm;          // [64][65]  transposed: Qt[d][m]
    float* Kt = sm + 4160;   // [64][65]  transposed: Kt[d][n]
    float* Vs = sm + 8320;   // [64][68]  natural:    Vs[n][d]  (16B-aligned rows)
    float* Ps = sm + 12672;  // [64][65]  Ps[m][n]

    const int tid = threadIdx.x;
    const int tx  = tid & 15;
    const int ty  = tid >> 4;
    const int bh  = blockIdx.y;
    const int b   = bh >> 3;
    const int h   = bh & 7;
    const int m0  = blockIdx.x << 6;
    const int base = bh * NS * NDH;

    // masked[] dtype hedge: int64 per reference, but tolerate int32.
    int len;
    {
        const long long* ml = (const long long*)masked_raw;
        long long probe = ml[0];
        if (probe >= 1 && probe <= NS) len = (int)ml[b];
        else                           len = ((const int*)masked_raw)[b];
    }

    const int lr  = tid >> 4;  // row slice for cooperative loads
    const int lc4 = tid & 15;  // float4 column

    // Load Q tile transposed (conflict-free writes: bank = 4*lc4+u+row)
#pragma unroll
    for (int rr = 0; rr < 4; ++rr) {
        int row = lr + rr * 16;
        float4 t4 = *(const float4*)(q + base + (m0 + row) * NDH + lc4 * 4);
        Qt[(lc4 * 4 + 0) * 65 + row] = t4.x;
        Qt[(lc4 * 4 + 1) * 65 + row] = t4.y;
        Qt[(lc4 * 4 + 2) * 65 + row] = t4.z;
        Qt[(lc4 * 4 + 3) * 65 + row] = t4.w;
    }

    float mr[4], lsumr[4], acc[4][4];
#pragma unroll
    for (int i = 0; i < 4; ++i) {
        mr[i] = -1e30f;
        lsumr[i] = 0.0f;
#pragma unroll
        for (int j = 0; j < 4; ++j) acc[i][j] = 0.0f;
    }

    const int ntiles = (len + 63) >> 6;
    for (int t = 0; t < ntiles; ++t) {
        int n0 = t << 6;
        __syncthreads();  // protect Kt/Vs/Ps from previous iteration's readers
#pragma unroll
        for (int rr = 0; rr < 4; ++rr) {
            int row = lr + rr * 16;
            float4 k4 = *(const float4*)(k + base + (n0 + row) * NDH + lc4 * 4);
            Kt[(lc4 * 4 + 0) * 65 + row] = k4.x;
            Kt[(lc4 * 4 + 1) * 65 + row] = k4.y;
            Kt[(lc4 * 4 + 2) * 65 + row] = k4.z;
            Kt[(lc4 * 4 + 3) * 65 + row] = k4.w;
            float4 v4 = *(const float4*)(v + base + (n0 + row) * NDH + lc4 * 4);
            *(float4*)(Vs + row * 68 + lc4 * 4) = v4;
        }
        __syncthreads();

        // S = Q K^T (q pre-scaled by 1/8)
        float s[4][4];
#pragma unroll
        for (int i = 0; i < 4; ++i)
#pragma unroll
            for (int j = 0; j < 4; ++j) s[i][j] = 0.0f;

#pragma unroll 8
        for (int kk = 0; kk < 64; ++kk) {
            float a0 = Qt[kk * 65 + 4 * ty + 0];
            float a1 = Qt[kk * 65 + 4 * ty + 1];
            float a2 = Qt[kk * 65 + 4 * ty + 2];
            float a3 = Qt[kk * 65 + 4 * ty + 3];
            float c0 = Kt[kk * 65 + tx +  0];
            float c1 = Kt[kk * 65 + tx + 16];
            float c2 = Kt[kk * 65 + tx + 32];
            float c3 = Kt[kk * 65 + tx + 48];
            s[0][0] = fmaf(a0, c0, s[0][0]); s[0][1] = fmaf(a0, c1, s[0][1]);
            s[0][2] = fmaf(a0, c2, s[0][2]); s[0][3] = fmaf(a0, c3, s[0][3]);
            s[1][0] = fmaf(a1, c0, s[1][0]); s[1][1] = fmaf(a1, c1, s[1][1]);
            s[1][2] = fmaf(a1, c2, s[1][2]); s[1][3] = fmaf(a1, c3, s[1][3]);
            s[2][0] = fmaf(a2, c0, s[2][0]); s[2][1] = fmaf(a2, c1, s[2][1]);
            s[2][2] = fmaf(a2, c2, s[2][2]); s[2][3] = fmaf(a2, c3, s[2][3]);
            s[3][0] = fmaf(a3, c0, s[3][0]); s[3][1] = fmaf(a3, c1, s[3][1]);
            s[3][2] = fmaf(a3, c2, s[3][2]); s[3][3] = fmaf(a3, c3, s[3][3]);
        }

        // key-length mask
#pragma unroll
        for (int j = 0; j < 4; ++j) {
            if (n0 + tx + 16 * j >= len) {
#pragma unroll
                for (int i = 0; i < 4; ++i) s[i][j] = NEGV;
            }
        }

        // online softmax update (per row, reduced over the 16 tx lanes)
#pragma unroll
        for (int i = 0; i < 4; ++i) {
            float tm = fmaxf(fmaxf(s[i][0], s[i][1]), fmaxf(s[i][2], s[i][3]));
#pragma unroll
            for (int off = 8; off > 0; off >>= 1)
                tm = fmaxf(tm, __shfl_xor_sync(0xffffffffu, tm, off));
            float mn = fmaxf(mr[i], tm);
            float sc = __expf(mr[i] - mn);
            mr[i] = mn;
            float ls = 0.0f;
#pragma unroll
            for (int j = 0; j < 4; ++j) {
                float p = __expf(s[i][j] - mn);
                Ps[(4 * ty + i) * 65 + tx + 16 * j] = p;
                ls += p;
            }
#pragma unroll
            for (int off = 8; off > 0; off >>= 1)
                ls += __shfl_xor_sync(0xffffffffu, ls, off);
            lsumr[i] = lsumr[i] * sc + ls;
#pragma unroll
            for (int j = 0; j < 4; ++j) acc[i][j] *= sc;
        }
        __syncthreads();

        // O += P V
#pragma unroll 8
        for (int n = 0; n < 64; ++n) {
            float p0 = Ps[(4 * ty + 0) * 65 + n];
            float p1 = Ps[(4 * ty + 1) * 65 + n];
            float p2 = Ps[(4 * ty + 2) * 65 + n];
            float p3 = Ps[(4 * ty + 3) * 65 + n];
            float w0 = Vs[n * 68 + tx +  0];
            float w1 = Vs[n * 68 + tx + 16];
            float w2 = Vs[n * 68 + tx + 32];
            float w3 = Vs[n * 68 + tx + 48];
            acc[0][0] = fmaf(p0, w0, acc[0][0]); acc[0][1] = fmaf(p0, w1, acc[0][1]);
            acc[0][2] = fmaf(p0, w2, acc[0][2]); acc[0][3] = fmaf(p0, w3, acc[0][3]);
            acc[1][0] = fmaf(p1, w0, acc[1][0]); acc[1][1] = fmaf(p1, w1, acc[1][1]);
            acc[1][2] = fmaf(p1, w2, acc[1][2]); acc[1][3] = fmaf(p1, w3, acc[1][3]);
            acc[2][0] = fmaf(p2, w0, acc[2][0]); acc[2][1] = fmaf(p2, w1, acc[2][1]);
            acc[2][2] = fmaf(p2, w2, acc[2][2]); acc[2][3] = fmaf(p2, w3, acc[2][3]);
            acc[3][0] = fmaf(p3, w0, acc[3][0]); acc[3][1] = fmaf(p3, w1, acc[3][1]);
            acc[3][2] = fmaf(p3, w2, acc[3][2]); acc[3][3] = fmaf(p3, w3, acc[3][3]);
        }
    }

    // normalize + write context in [B,S,D] layout
#pragma unroll
    for (int i = 0; i < 4; ++i) {
        float inv = 1.0f / lsumr[i];
        int m = m0 + 4 * ty + i;
        int ob = (b * NS + m) * ND + h * 64;
#pragma unroll
        for (int j = 0; j < 4; ++j)
            ctx[ob + tx + 16 * j] = acc[i][j] * inv;
    }
}

// ---------------------------------------------------------------------------
extern "C" void kernel_launch(void* const* d_in, const int* in_sizes, int n_in,
                              void* d_out, int out_size)
{
    (void)in_sizes; (void)n_in; (void)out_size;
    const float* Q  = (const float*)d_in[0];
    const float* K  = (const float*)d_in[1];
    const float* V  = (const float*)d_in[2];
    const float* Wq = (const float*)d_in[3];
    const float* bq = (const float*)d_in[4];
    const float* Wk = (const float*)d_in[5];
    const float* bk = (const float*)d_in[6];
    const float* Wv = (const float*)d_in[7];
    const float* bv = (const float*)d_in[8];
    const float* Wo = (const float*)d_in[9];
    const float* bo = (const float*)d_in[10];
    const void*  mk = d_in[11];
    float* out = (float*)d_out;

    float *pq, *pk, *pv, *pctx;
    cudaGetSymbolAddress((void**)&pq,   g_q);
    cudaGetSymbolAddress((void**)&pk,   g_k);
    cudaGetSymbolAddress((void**)&pv,   g_v);
    cudaGetSymbolAddress((void**)&pctx, g_ctx);

    dim3 gp(64, 4);  // M/128 = 64, N/128 = 4
    proj_kernel<1><<<gp, 256>>>(Q, Wq, bq, pq, 0.125f);  // 1/sqrt(64) folded into q
    proj_kernel<1><<<gp, 256>>>(K, Wk, bk, pk, 1.0f);
    proj_kernel<1><<<gp, 256>>>(V, Wv, bv, pv, 1.0f);

    const int smem = 16832 * 4;  // Qt+Kt+Ps (64x65) + Vs (64x68)
    cudaFuncSetAttribute(attn_kernel, cudaFuncAttributeMaxDynamicSharedMemorySize, smem);
    attn_kernel<<<dim3(NS / 64, NB * NH), 256, smem>>>(pq, pk, pv, pctx, mk);

    proj_kernel<0><<<gp, 256>>>(pctx, Wo, bo, out, 1.0f);
}

// round 3
// speedup vs baseline: 1.7009x; 1.7009x over previous
#include <cuda_runtime.h>
#include <cuda_bf16.h>
#include <cstdint>

#define NB  4
#define NS  2048
#define ND  512
#define NH  8
#define NDH 64
#define NEGV -1000000.0f

// ---------------------------------------------------------------------------
// Scratch (device globals: allocation-free rule)
// ---------------------------------------------------------------------------
__device__ float g_q[NB * NH * NS * NDH];       // [B,H,S,64], pre-scaled
__device__ float g_k[NB * NH * NS * NDH];
__device__ float g_v[NB * NH * NS * NDH];
__device__ float g_ctx[NB * NS * ND];           // [B,S,D]
__device__ __nv_bfloat16 g_ah[NB * NS * ND];    // activation hi (reused per proj)
__device__ __nv_bfloat16 g_al[NB * NS * ND];    // activation lo
__device__ __nv_bfloat16 g_wh[ND * ND];         // weight hi
__device__ __nv_bfloat16 g_wl[ND * ND];         // weight lo

// ---------------------------------------------------------------------------
__device__ __forceinline__ uint32_t smem_u32(const void* p) {
    uint32_t a;
    asm("{ .reg .u64 t; cvta.to.shared.u64 t, %1; cvt.u32.u64 %0, t; }"
        : "=r"(a) : "l"(p));
    return a;
}

__device__ __forceinline__ void cp_async16(uint32_t dst, const void* src) {
    asm volatile("cp.async.ca.shared.global [%0], [%1], 16;"
                 :: "r"(dst), "l"(src) : "memory");
}
__device__ __forceinline__ void cp_commit() {
    asm volatile("cp.async.commit_group;" ::: "memory");
}

__device__ __forceinline__ void ldsm_x4(uint32_t addr, uint32_t& r0, uint32_t& r1,
                                        uint32_t& r2, uint32_t& r3) {
    asm volatile("ldmatrix.sync.aligned.m8n8.x4.shared.b16 {%0,%1,%2,%3}, [%4];"
                 : "=r"(r0), "=r"(r1), "=r"(r2), "=r"(r3) : "r"(addr));
}

__device__ __forceinline__ void mma16816(float* c, const uint32_t* a, const uint32_t* b) {
    asm volatile(
        "mma.sync.aligned.m16n8k16.row.col.f32.bf16.bf16.f32 "
        "{%0,%1,%2,%3}, {%4,%5,%6,%7}, {%8,%9}, {%0,%1,%2,%3};"
        : "+f"(c[0]), "+f"(c[1]), "+f"(c[2]), "+f"(c[3])
        : "r"(a[0]), "r"(a[1]), "r"(a[2]), "r"(a[3]), "r"(b[0]), "r"(b[1]));
}

// ---------------------------------------------------------------------------
// fp32 -> bf16 hi/lo split conversion (vectorized)
// ---------------------------------------------------------------------------
__global__ __launch_bounds__(256) void conv_kernel(
    const float* __restrict__ in, __nv_bfloat16* __restrict__ hi,
    __nv_bfloat16* __restrict__ lo, int n4)
{
    int idx = blockIdx.x * 256 + threadIdx.x;
    if (idx >= n4) return;
    float4 v = ((const float4*)in)[idx];
    float f[4] = {v.x, v.y, v.z, v.w};
    __nv_bfloat16 h[4], l[4];
#pragma unroll
    for (int i = 0; i < 4; ++i) {
        h[i] = __float2bfloat16_rn(f[i]);
        l[i] = __float2bfloat16_rn(f[i] - __bfloat162float(h[i]));
    }
    ((uint2*)hi)[idx] = *(uint2*)h;
    ((uint2*)lo)[idx] = *(uint2*)l;
}

// ---------------------------------------------------------------------------
// HMMA projection GEMM: C[8192,512] = X @ W^T + bias (bf16 hi/lo, 3 products)
// CTA 128x128, BK=32, cp.async double-buffered, 8 warps @ 32x64.
// MODE 0: row-major out. MODE 1: scatter to [B,H,S,64] with scale.
// ---------------------------------------------------------------------------
// SMEM per stage: Ah, Al, Bh, Bl each 128 rows x (32+8) bf16 = 10240 B
#define ROWB   80       // bytes per smem row (40 bf16)
#define ARRSZ  10240
#define STAGESZ (4 * ARRSZ)
#define PROJ_SMEM (2 * STAGESZ)

template <int MODE>
__global__ __launch_bounds__(256) void proj_hmma(
    const __nv_bfloat16* __restrict__ Ah, const __nv_bfloat16* __restrict__ Al,
    const __nv_bfloat16* __restrict__ Bh, const __nv_bfloat16* __restrict__ Bl,
    const float* __restrict__ bias, float* __restrict__ out, float scale)
{
    extern __shared__ char smem[];
    const uint32_t sb = smem_u32(smem);
    const int tid  = threadIdx.x;
    const int lane = tid & 31;
    const int wid  = tid >> 5;
    const int warp_m = wid & 3;       // 0..3 -> m offset 32*warp_m
    const int warp_n = wid >> 2;      // 0..1 -> n offset 64*warp_n
    const int m0 = blockIdx.x * 128;
    const int n0 = blockIdx.y * 128;

    // cp.async indexing: 2 segments per array per thread per chunk
    const int r0c = (tid + 0)   >> 2, s0c = tid & 3;
    const int r1c = (tid + 256) >> 2, s1c = tid & 3;  // row +64, same seg

    // ldmatrix per-thread offsets (bytes within an array)
    const uint32_t a_off = (uint32_t)((warp_m * 32 + (lane & 15)) * ROWB + (lane >> 4) * 16);
    const uint32_t b_off = (uint32_t)((warp_n * 64 + (lane & 7) + 8 * (lane >> 4)) * ROWB
                                      + ((lane >> 3) & 1) * 16);

    float acc[2][8][4];
#pragma unroll
    for (int mi = 0; mi < 2; ++mi)
#pragma unroll
        for (int ni = 0; ni < 8; ++ni)
#pragma unroll
            for (int q = 0; q < 4; ++q) acc[mi][ni][q] = 0.0f;

    auto load_chunk = [&](int c, int stage) {
        const int k0 = c * 32;
        const uint32_t st = sb + stage * STAGESZ;
        // A rows from m0, B rows from n0 (W is [n][k])
        const __nv_bfloat16* srcs[4] = {Ah, Al, Bh, Bl};
#pragma unroll
        for (int arr = 0; arr < 4; ++arr) {
            const __nv_bfloat16* base = srcs[arr];
            const int rbase = (arr < 2) ? m0 : n0;
            cp_async16(st + arr * ARRSZ + r0c * ROWB + s0c * 16,
                       base + (rbase + r0c) * ND + k0 + s0c * 8);
            cp_async16(st + arr * ARRSZ + r1c * ROWB + s1c * 16,
                       base + (rbase + r1c) * ND + k0 + s1c * 8);
        }
        cp_commit();
    };

    load_chunk(0, 0);

    for (int c = 0; c < 16; ++c) {
        const int stage = c & 1;
        if (c < 15) load_chunk(c + 1, stage ^ 1);
        if (c < 15) asm volatile("cp.async.wait_group 1;" ::: "memory");
        else        asm volatile("cp.async.wait_group 0;" ::: "memory");
        __syncthreads();

        const uint32_t st = sb + stage * STAGESZ;
#pragma unroll
        for (int ks = 0; ks < 2; ++ks) {
            const uint32_t kb = ks * 32;  // 16 bf16 = 32 bytes
            uint32_t ah[2][4], al[2][4];
#pragma unroll
            for (int mi = 0; mi < 2; ++mi) {
                uint32_t adr = st + a_off + mi * (16 * ROWB) + kb;
                ldsm_x4(adr,           ah[mi][0], ah[mi][1], ah[mi][2], ah[mi][3]);
                ldsm_x4(adr + ARRSZ,   al[mi][0], al[mi][1], al[mi][2], al[mi][3]);
            }
            uint32_t bh[8][2], bl[8][2];
#pragma unroll
            for (int nb = 0; nb < 4; ++nb) {
                uint32_t adr = st + 2 * ARRSZ + b_off + nb * (16 * ROWB) + kb;
                uint32_t t0, t1, t2, t3;
                ldsm_x4(adr, t0, t1, t2, t3);
                bh[nb*2][0] = t0; bh[nb*2][1] = t1; bh[nb*2+1][0] = t2; bh[nb*2+1][1] = t3;
                ldsm_x4(adr + ARRSZ, t0, t1, t2, t3);
                bl[nb*2][0] = t0; bl[nb*2][1] = t1; bl[nb*2+1][0] = t2; bl[nb*2+1][1] = t3;
            }
#pragma unroll
            for (int mi = 0; mi < 2; ++mi)
#pragma unroll
                for (int ni = 0; ni < 8; ++ni) {
                    mma16816(acc[mi][ni], ah[mi], bh[ni]);
                    mma16816(acc[mi][ni], ah[mi], bl[ni]);
                    mma16816(acc[mi][ni], al[mi], bh[ni]);
                }
        }
        __syncthreads();
    }

    // Epilogue: direct register -> gmem (float2 per fragment row)
    const int crow = lane >> 2;
    const int ccol = (lane & 3) * 2;
#pragma unroll
    for (int mi = 0; mi < 2; ++mi) {
#pragma unroll
        for (int half = 0; half < 2; ++half) {
            const int m = m0 + warp_m * 32 + mi * 16 + crow + half * 8;
            const int b = m >> 11, s = m & 2047;
#pragma unroll
            for (int ni = 0; ni < 8; ++ni) {
                const int n = n0 + warp_n * 64 + ni * 8 + ccol;
                float v0 = acc[mi][ni][half * 2 + 0] + bias[n];
                float v1 = acc[mi][ni][half * 2 + 1] + bias[n + 1];
                if (MODE == 1) {
                    v0 *= scale; v1 *= scale;
                    const int head = n >> 6, d = n & 63;
                    float2* p = (float2*)&out[(((b * NH + head) * NS) + s) * NDH + d];
                    *p = make_float2(v0, v1);
                } else {
                    *(float2*)&out[m * ND + n] = make_float2(v0, v1);
                }
            }
        }
    }
}

// ---------------------------------------------------------------------------
// Flash attention (fp32 SIMT) — unchanged (322us; next round's target).
// ---------------------------------------------------------------------------
__global__ __launch_bounds__(256) void attn_kernel(
    const float* __restrict__ q, const float* __restrict__ k,
    const float* __restrict__ v, float* __restrict__ ctx,
    const void* __restrict__ masked_raw)
{
    extern __shared__ float sm[];
    float* Qt = sm;          // [64][65]
    float* Kt = sm + 4160;   // [64][65]
    float* Vs = sm + 8320;   // [64][68]
    float* Ps = sm + 12672;  // [64][65]

    const int tid = threadIdx.x;
    const int tx  = tid & 15;
    const int ty  = tid >> 4;
    const int bh  = blockIdx.y;
    const int b   = bh >> 3;
    const int h   = bh & 7;
    const int m0  = blockIdx.x << 6;
    const int base = bh * NS * NDH;

    int len;
    {
        const long long* ml = (const long long*)masked_raw;
        long long probe = ml[0];
        if (probe >= 1 && probe <= NS) len = (int)ml[b];
        else                           len = ((const int*)masked_raw)[b];
    }

    const int lr  = tid >> 4;
    const int lc4 = tid & 15;

#pragma unroll
    for (int rr = 0; rr < 4; ++rr) {
        int row = lr + rr * 16;
        float4 t4 = *(const float4*)(q + base + (m0 + row) * NDH + lc4 * 4);
        Qt[(lc4 * 4 + 0) * 65 + row] = t4.x;
        Qt[(lc4 * 4 + 1) * 65 + row] = t4.y;
        Qt[(lc4 * 4 + 2) * 65 + row] = t4.z;
        Qt[(lc4 * 4 + 3) * 65 + row] = t4.w;
    }

    float mr[4], lsumr[4], acc[4][4];
#pragma unroll
    for (int i = 0; i < 4; ++i) {
        mr[i] = -1e30f;
        lsumr[i] = 0.0f;
#pragma unroll
        for (int j = 0; j < 4; ++j) acc[i][j] = 0.0f;
    }

    const int ntiles = (len + 63) >> 6;
    for (int t = 0; t < ntiles; ++t) {
        int n0 = t << 6;
        __syncthreads();
#pragma unroll
        for (int rr = 0; rr < 4; ++rr) {
            int row = lr + rr * 16;
            float4 k4 = *(const float4*)(k + base + (n0 + row) * NDH + lc4 * 4);
            Kt[(lc4 * 4 + 0) * 65 + row] = k4.x;
            Kt[(lc4 * 4 + 1) * 65 + row] = k4.y;
            Kt[(lc4 * 4 + 2) * 65 + row] = k4.z;
            Kt[(lc4 * 4 + 3) * 65 + row] = k4.w;
            float4 v4 = *(const float4*)(v + base + (n0 + row) * NDH + lc4 * 4);
            *(float4*)(Vs + row * 68 + lc4 * 4) = v4;
        }
        __syncthreads();

        float s[4][4];
#pragma unroll
        for (int i = 0; i < 4; ++i)
#pragma unroll
            for (int j = 0; j < 4; ++j) s[i][j] = 0.0f;

#pragma unroll 8
        for (int kk = 0; kk < 64; ++kk) {
            float a0 = Qt[kk * 65 + 4 * ty + 0];
            float a1 = Qt[kk * 65 + 4 * ty + 1];
            float a2 = Qt[kk * 65 + 4 * ty + 2];
            float a3 = Qt[kk * 65 + 4 * ty + 3];
            float c0 = Kt[kk * 65 + tx +  0];
            float c1 = Kt[kk * 65 + tx + 16];
            float c2 = Kt[kk * 65 + tx + 32];
            float c3 = Kt[kk * 65 + tx + 48];
            s[0][0] = fmaf(a0, c0, s[0][0]); s[0][1] = fmaf(a0, c1, s[0][1]);
            s[0][2] = fmaf(a0, c2, s[0][2]); s[0][3] = fmaf(a0, c3, s[0][3]);
            s[1][0] = fmaf(a1, c0, s[1][0]); s[1][1] = fmaf(a1, c1, s[1][1]);
            s[1][2] = fmaf(a1, c2, s[1][2]); s[1][3] = fmaf(a1, c3, s[1][3]);
            s[2][0] = fmaf(a2, c0, s[2][0]); s[2][1] = fmaf(a2, c1, s[2][1]);
            s[2][2] = fmaf(a2, c2, s[2][2]); s[2][3] = fmaf(a2, c3, s[2][3]);
            s[3][0] = fmaf(a3, c0, s[3][0]); s[3][1] = fmaf(a3, c1, s[3][1]);
            s[3][2] = fmaf(a3, c2, s[3][2]); s[3][3] = fmaf(a3, c3, s[3][3]);
        }

#pragma unroll
        for (int j = 0; j < 4; ++j) {
            if (n0 + tx + 16 * j >= len) {
#pragma unroll
                for (int i = 0; i < 4; ++i) s[i][j] = NEGV;
            }
        }

#pragma unroll
        for (int i = 0; i < 4; ++i) {
            float tm = fmaxf(fmaxf(s[i][0], s[i][1]), fmaxf(s[i][2], s[i][3]));
#pragma unroll
            for (int off = 8; off > 0; off >>= 1)
                tm = fmaxf(tm, __shfl_xor_sync(0xffffffffu, tm, off));
            float mn = fmaxf(mr[i], tm);
            float sc = __expf(mr[i] - mn);
            mr[i] = mn;
            float ls = 0.0f;
#pragma unroll
            for (int j = 0; j < 4; ++j) {
                float p = __expf(s[i][j] - mn);
                Ps[(4 * ty + i) * 65 + tx + 16 * j] = p;
                ls += p;
            }
#pragma unroll
            for (int off = 8; off > 0; off >>= 1)
                ls += __shfl_xor_sync(0xffffffffu, ls, off);
            lsumr[i] = lsumr[i] * sc + ls;
#pragma unroll
            for (int j = 0; j < 4; ++j) acc[i][j] *= sc;
        }
        __syncthreads();

#pragma unroll 8
        for (int n = 0; n < 64; ++n) {
            float p0 = Ps[(4 * ty + 0) * 65 + n];
            float p1 = Ps[(4 * ty + 1) * 65 + n];
            float p2 = Ps[(4 * ty + 2) * 65 + n];
            float p3 = Ps[(4 * ty + 3) * 65 + n];
            float w0 = Vs[n * 68 + tx +  0];
            float w1 = Vs[n * 68 + tx + 16];
            float w2 = Vs[n * 68 + tx + 32];
            float w3 = Vs[n * 68 + tx + 48];
            acc[0][0] = fmaf(p0, w0, acc[0][0]); acc[0][1] = fmaf(p0, w1, acc[0][1]);
            acc[0][2] = fmaf(p0, w2, acc[0][2]); acc[0][3] = fmaf(p0, w3, acc[0][3]);
            acc[1][0] = fmaf(p1, w0, acc[1][0]); acc[1][1] = fmaf(p1, w1, acc[1][1]);
            acc[1][2] = fmaf(p1, w2, acc[1][2]); acc[1][3] = fmaf(p1, w3, acc[1][3]);
            acc[2][0] = fmaf(p2, w0, acc[2][0]); acc[2][1] = fmaf(p2, w1, acc[2][1]);
            acc[2][2] = fmaf(p2, w2, acc[2][2]); acc[2][3] = fmaf(p2, w3, acc[2][3]);
            acc[3][0] = fmaf(p3, w0, acc[3][0]); acc[3][1] = fmaf(p3, w1, acc[3][1]);
            acc[3][2] = fmaf(p3, w2, acc[3][2]); acc[3][3] = fmaf(p3, w3, acc[3][3]);
        }
    }

#pragma unroll
    for (int i = 0; i < 4; ++i) {
        float inv = 1.0f / lsumr[i];
        int m = m0 + 4 * ty + i;
        int ob = (b * NS + m) * ND + h * 64;
#pragma unroll
        for (int j = 0; j < 4; ++j)
            ctx[ob + tx + 16 * j] = acc[i][j] * inv;
    }
}

// ---------------------------------------------------------------------------
extern "C" void kernel_launch(void* const* d_in, const int* in_sizes, int n_in,
                              void* d_out, int out_size)
{
    (void)in_sizes; (void)n_in; (void)out_size;
    const float* Q  = (const float*)d_in[0];
    const float* K  = (const float*)d_in[1];
    const float* V  = (const float*)d_in[2];
    const float* Wq = (const float*)d_in[3];
    const float* bq = (const float*)d_in[4];
    const float* Wk = (const float*)d_in[5];
    const float* bk = (const float*)d_in[6];
    const float* Wv = (const float*)d_in[7];
    const float* bv = (const float*)d_in[8];
    const float* Wo = (const float*)d_in[9];
    const float* bo = (const float*)d_in[10];
    const void*  mk = d_in[11];
    float* out = (float*)d_out;

    float *pq, *pk, *pv, *pctx;
    __nv_bfloat16 *pah, *pal, *pwh, *pwl;
    cudaGetSymbolAddress((void**)&pq,   g_q);
    cudaGetSymbolAddress((void**)&pk,   g_k);
    cudaGetSymbolAddress((void**)&pv,   g_v);
    cudaGetSymbolAddress((void**)&pctx, g_ctx);
    cudaGetSymbolAddress((void**)&pah,  g_ah);
    cudaGetSymbolAddress((void**)&pal,  g_al);
    cudaGetSymbolAddress((void**)&pwh,  g_wh);
    cudaGetSymbolAddress((void**)&pwl,  g_wl);

    const int nx4 = (NB * NS * ND) / 4;   // activation float4 count
    const int nw4 = (ND * ND) / 4;        // weight float4 count

    cudaFuncSetAttribute(proj_hmma<1>, cudaFuncAttributeMaxDynamicSharedMemorySize, PROJ_SMEM);
    cudaFuncSetAttribute(proj_hmma<0>, cudaFuncAttributeMaxDynamicSharedMemorySize, PROJ_SMEM);

    dim3 gp(64, 4);

    // Q projection (scale 1/sqrt(64) folded into q)
    conv_kernel<<<(nx4 + 255) / 256, 256>>>(Q,  pah, pal, nx4);
    conv_kernel<<<(nw4 + 255) / 256, 256>>>(Wq, pwh, pwl, nw4);
    proj_hmma<1><<<gp, 256, PROJ_SMEM>>>(pah, pal, pwh, pwl, bq, pq, 0.125f);
    // K projection
    conv_kernel<<<(nx4 + 255) / 256, 256>>>(K,  pah, pal, nx4);
    conv_kernel<<<(nw4 + 255) / 256, 256>>>(Wk, pwh, pwl, nw4);
    proj_hmma<1><<<gp, 256, PROJ_SMEM>>>(pah, pal, pwh, pwl, bk, pk, 1.0f);
    // V projection
    conv_kernel<<<(nx4 + 255) / 256, 256>>>(V,  pah, pal, nx4);
    conv_kernel<<<(nw4 + 255) / 256, 256>>>(Wv, pwh, pwl, nw4);
    proj_hmma<1><<<gp, 256, PROJ_SMEM>>>(pah, pal, pwh, pwl, bv, pv, 1.0f);

    // Attention
    const int asmem = 16832 * 4;
    cudaFuncSetAttribute(attn_kernel, cudaFuncAttributeMaxDynamicSharedMemorySize, asmem);
    attn_kernel<<<dim3(NS / 64, NB * NH), 256, asmem>>>(pq, pk, pv, pctx, mk);

    // Output projection
    conv_kernel<<<(nx4 + 255) / 256, 256>>>(pctx, pah, pal, nx4);
    conv_kernel<<<(nw4 + 255) / 256, 256>>>(Wo,   pwh, pwl, nw4);
    proj_hmma<0><<<gp, 256, PROJ_SMEM>>>(pah, pal, pwh, pwl, bo, out, 1.0f);
}

// round 4
// speedup vs baseline: 2.9167x; 1.7148x over previous
#include <cuda_runtime.h>
#include <cuda_bf16.h>
#include <cstdint>

#define NB  4
#define NS  2048
#define ND  512
#define NH  8
#define NDH 64

// ---------------------------------------------------------------------------
// Scratch (device globals: allocation-free rule)
// ---------------------------------------------------------------------------
__device__ __nv_bfloat16 g_qh[NB * NH * NS * NDH];
__device__ __nv_bfloat16 g_ql[NB * NH * NS * NDH];
__device__ __nv_bfloat16 g_kh[NB * NH * NS * NDH];
__device__ __nv_bfloat16 g_kl[NB * NH * NS * NDH];
__device__ __nv_bfloat16 g_vh[NB * NH * NS * NDH];
__device__ __nv_bfloat16 g_vl[NB * NH * NS * NDH];
__device__ __nv_bfloat16 g_ah[NB * NS * ND];   // activation splits / ctx hi
__device__ __nv_bfloat16 g_al[NB * NS * ND];   // activation splits / ctx lo
__device__ __nv_bfloat16 g_wh[ND * ND];
__device__ __nv_bfloat16 g_wl[ND * ND];

// ---------------------------------------------------------------------------
__device__ __forceinline__ uint32_t smem_u32(const void* p) {
    uint32_t a;
    asm("{ .reg .u64 t; cvta.to.shared.u64 t, %1; cvt.u32.u64 %0, t; }"
        : "=r"(a) : "l"(p));
    return a;
}
__device__ __forceinline__ void cp_async16(uint32_t dst, const void* src) {
    asm volatile("cp.async.ca.shared.global [%0], [%1], 16;"
                 :: "r"(dst), "l"(src) : "memory");
}
__device__ __forceinline__ void cp_commit() {
    asm volatile("cp.async.commit_group;" ::: "memory");
}
__device__ __forceinline__ void ldsm_x4(uint32_t addr, uint32_t& r0, uint32_t& r1,
                                        uint32_t& r2, uint32_t& r3) {
    asm volatile("ldmatrix.sync.aligned.m8n8.x4.shared.b16 {%0,%1,%2,%3}, [%4];"
                 : "=r"(r0), "=r"(r1), "=r"(r2), "=r"(r3) : "r"(addr));
}
__device__ __forceinline__ void ldsm_x4_t(uint32_t addr, uint32_t& r0, uint32_t& r1,
                                          uint32_t& r2, uint32_t& r3) {
    asm volatile("ldmatrix.sync.aligned.m8n8.x4.trans.shared.b16 {%0,%1,%2,%3}, [%4];"
                 : "=r"(r0), "=r"(r1), "=r"(r2), "=r"(r3) : "r"(addr));
}
__device__ __forceinline__ void mma16816(float* c, const uint32_t* a, const uint32_t* b) {
    asm volatile(
        "mma.sync.aligned.m16n8k16.row.col.f32.bf16.bf16.f32 "
        "{%0,%1,%2,%3}, {%4,%5,%6,%7}, {%8,%9}, {%0,%1,%2,%3};"
        : "+f"(c[0]), "+f"(c[1]), "+f"(c[2]), "+f"(c[3])
        : "r"(a[0]), "r"(a[1]), "r"(a[2]), "r"(a[3]), "r"(b[0]), "r"(b[1]));
}
__device__ __forceinline__ float ex2(float x) {
    float y;
    asm("ex2.approx.ftz.f32 %0, %1;" : "=f"(y) : "f"(x));
    return y;
}
__device__ __forceinline__ uint32_t pack_bf2(float a, float b) {
    __nv_bfloat162 t = __floats2bfloat162_rn(a, b);
    return *(uint32_t*)&t;
}

// ---------------------------------------------------------------------------
// fp32 -> bf16 hi/lo split conversion
// ---------------------------------------------------------------------------
__global__ __launch_bounds__(256) void conv_kernel(
    const float* __restrict__ in, __nv_bfloat16* __restrict__ hi,
    __nv_bfloat16* __restrict__ lo, int n4)
{
    int idx = blockIdx.x * 256 + threadIdx.x;
    if (idx >= n4) return;
    float4 v = ((const float4*)in)[idx];
    float f[4] = {v.x, v.y, v.z, v.w};
    __nv_bfloat16 h[4], l[4];
#pragma unroll
    for (int i = 0; i < 4; ++i) {
        h[i] = __float2bfloat16_rn(f[i]);
        l[i] = __float2bfloat16_rn(f[i] - __bfloat162float(h[i]));
    }
    ((uint2*)hi)[idx] = *(uint2*)h;
    ((uint2*)lo)[idx] = *(uint2*)l;
}

// ---------------------------------------------------------------------------
// HMMA projection GEMM: C[8192,512] = X @ W^T + bias (bf16 hi/lo, 3 products)
// MODE 0: fp32 row-major out. MODE 1: bf16 hi/lo out, head layout, scaled.
// ---------------------------------------------------------------------------
#define ROWB   80
#define ARRSZ  10240
#define STAGESZ (4 * ARRSZ)
#define PROJ_SMEM (2 * STAGESZ)

template <int MODE>
__global__ __launch_bounds__(256) void proj_hmma(
    const __nv_bfloat16* __restrict__ Ah, const __nv_bfloat16* __restrict__ Al,
    const __nv_bfloat16* __restrict__ Bh, const __nv_bfloat16* __restrict__ Bl,
    const float* __restrict__ bias, float* __restrict__ outF,
    __nv_bfloat16* __restrict__ outH, __nv_bfloat16* __restrict__ outL,
    float scale)
{
    extern __shared__ char smem[];
    const uint32_t sb = smem_u32(smem);
    const int tid  = threadIdx.x;
    const int lane = tid & 31;
    const int wid  = tid >> 5;
    const int warp_m = wid & 3;
    const int warp_n = wid >> 2;
    const int m0 = blockIdx.x * 128;
    const int n0 = blockIdx.y * 128;

    const int r0c = (tid + 0)   >> 2, s0c = tid & 3;
    const int r1c = (tid + 256) >> 2, s1c = tid & 3;

    const uint32_t a_off = (uint32_t)((warp_m * 32 + (lane & 15)) * ROWB + (lane >> 4) * 16);
    const uint32_t b_off = (uint32_t)((warp_n * 64 + (lane & 7) + 8 * (lane >> 4)) * ROWB
                                      + ((lane >> 3) & 1) * 16);

    float acc[2][8][4];
#pragma unroll
    for (int mi = 0; mi < 2; ++mi)
#pragma unroll
        for (int ni = 0; ni < 8; ++ni)
#pragma unroll
            for (int q = 0; q < 4; ++q) acc[mi][ni][q] = 0.0f;

    auto load_chunk = [&](int c, int stage) {
        const int k0 = c * 32;
        const uint32_t st = sb + stage * STAGESZ;
        const __nv_bfloat16* srcs[4] = {Ah, Al, Bh, Bl};
#pragma unroll
        for (int arr = 0; arr < 4; ++arr) {
            const __nv_bfloat16* base = srcs[arr];
            const int rbase = (arr < 2) ? m0 : n0;
            cp_async16(st + arr * ARRSZ + r0c * ROWB + s0c * 16,
                       base + (rbase + r0c) * ND + k0 + s0c * 8);
            cp_async16(st + arr * ARRSZ + r1c * ROWB + s1c * 16,
                       base + (rbase + r1c) * ND + k0 + s1c * 8);
        }
        cp_commit();
    };

    load_chunk(0, 0);

    for (int c = 0; c < 16; ++c) {
        const int stage = c & 1;
        if (c < 15) {
            load_chunk(c + 1, stage ^ 1);
            asm volatile("cp.async.wait_group 1;" ::: "memory");
        } else {
            asm volatile("cp.async.wait_group 0;" ::: "memory");
        }
        __syncthreads();

        const uint32_t st = sb + stage * STAGESZ;
#pragma unroll
        for (int ks = 0; ks < 2; ++ks) {
            const uint32_t kb = ks * 32;
            uint32_t ah[2][4], al[2][4];
#pragma unroll
            for (int mi = 0; mi < 2; ++mi) {
                uint32_t adr = st + a_off + mi * (16 * ROWB) + kb;
                ldsm_x4(adr,         ah[mi][0], ah[mi][1], ah[mi][2], ah[mi][3]);
                ldsm_x4(adr + ARRSZ, al[mi][0], al[mi][1], al[mi][2], al[mi][3]);
            }
            uint32_t bh[8][2], bl[8][2];
#pragma unroll
            for (int nb = 0; nb < 4; ++nb) {
                uint32_t adr = st + 2 * ARRSZ + b_off + nb * (16 * ROWB) + kb;
                uint32_t t0, t1, t2, t3;
                ldsm_x4(adr, t0, t1, t2, t3);
                bh[nb*2][0] = t0; bh[nb*2][1] = t1; bh[nb*2+1][0] = t2; bh[nb*2+1][1] = t3;
                ldsm_x4(adr + ARRSZ, t0, t1, t2, t3);
                bl[nb*2][0] = t0; bl[nb*2][1] = t1; bl[nb*2+1][0] = t2; bl[nb*2+1][1] = t3;
            }
#pragma unroll
            for (int mi = 0; mi < 2; ++mi)
#pragma unroll
                for (int ni = 0; ni < 8; ++ni) {
                    mma16816(acc[mi][ni], ah[mi], bh[ni]);
                    mma16816(acc[mi][ni], ah[mi], bl[ni]);
                    mma16816(acc[mi][ni], al[mi], bh[ni]);
                }
        }
        __syncthreads();
    }

    const int crow = lane >> 2;
    const int ccol = (lane & 3) * 2;
#pragma unroll
    for (int mi = 0; mi < 2; ++mi) {
#pragma unroll
        for (int half = 0; half < 2; ++half) {
            const int m = m0 + warp_m * 32 + mi * 16 + crow + half * 8;
            const int b = m >> 11, s = m & 2047;
#pragma unroll
            for (int ni = 0; ni < 8; ++ni) {
                const int n = n0 + warp_n * 64 + ni * 8 + ccol;
                float v0 = acc[mi][ni][half * 2 + 0] + bias[n];
                float v1 = acc[mi][ni][half * 2 + 1] + bias[n + 1];
                if (MODE == 1) {
                    v0 *= scale; v1 *= scale;
                    const int head = n >> 6, d = n & 63;
                    const int idx = ((b * NH + head) * NS + s) * NDH + d;
                    __nv_bfloat16 h0 = __float2bfloat16_rn(v0);
                    __nv_bfloat16 h1 = __float2bfloat16_rn(v1);
                    float l0 = v0 - __bfloat162float(h0);
                    float l1 = v1 - __bfloat162float(h1);
                    *(uint32_t*)&outH[idx] = pack_bf2(__bfloat162float(h0), __bfloat162float(h1));
                    *(uint32_t*)&outL[idx] = pack_bf2(l0, l1);
                } else {
                    *(float2*)&outF[m * ND + n] = make_float2(v0, v1);
                }
            }
        }
    }
}

// ---------------------------------------------------------------------------
// HMMA flash attention. CTA = 128 q rows x one (b,h). 8 warps x 16 rows.
// KV tile 128, cp.async double-buffered. q pre-scaled by 0.125*log2(e);
// softmax in log2 domain. S and PV via bf16 hi/lo (3 MMAs each).
// Writes ctx as bf16 hi/lo [B,S,D].
// ---------------------------------------------------------------------------
// SMEM: Qh @0, Ql @18432 (128 x 144B rows)
//       stage s @ 36864 + s*73728: Kh +0, Kl +18432, Vh +36864, Vl +55296
#define QROWB 144
#define KARR  18432
#define KVSTAGE (4 * KARR)
#define ATTN_SMEM (2 * KARR + 2 * KVSTAGE)   // 184320

__global__ __launch_bounds__(256, 1) void attn_hmma(
    const __nv_bfloat16* __restrict__ qh, const __nv_bfloat16* __restrict__ ql,
    const __nv_bfloat16* __restrict__ kh, const __nv_bfloat16* __restrict__ kl,
    const __nv_bfloat16* __restrict__ vh, const __nv_bfloat16* __restrict__ vl,
    __nv_bfloat16* __restrict__ ch, __nv_bfloat16* __restrict__ cl,
    const void* __restrict__ masked_raw)
{
    extern __shared__ char smem[];
    const uint32_t sb = smem_u32(smem);
    const int tid  = threadIdx.x;
    const int lane = tid & 31;
    const int wid  = tid >> 5;
    const int bh   = blockIdx.y;
    const int b    = bh >> 3;
    const int h    = bh & 7;
    const int q0   = blockIdx.x << 7;
    const int gbase = bh * NS * NDH;

    int len;
    {
        const long long* ml = (const long long*)masked_raw;
        long long probe = ml[0];
        if (probe >= 1 && probe <= NS) len = (int)ml[b];
        else                           len = ((const int*)masked_raw)[b];
    }
    const int ntiles = (len + 127) >> 7;

    // Load Q hi/lo into smem (plain 16B loads)
#pragma unroll
    for (int i = 0; i < 4; ++i) {
        int c = tid + i * 256;            // 0..1023
        int r = c >> 3, blk = c & 7;
        const int src = gbase + (q0 + r) * NDH + blk * 8;
        *(uint4*)(smem + r * QROWB + blk * 16)         = *(const uint4*)(qh + src);
        *(uint4*)(smem + KARR + r * QROWB + blk * 16)  = *(const uint4*)(ql + src);
    }

    auto load_kv = [&](int t, int stg) {
        const uint32_t s0 = sb + 2 * KARR + stg * KVSTAGE;
        const int gk = gbase + (t << 7) * NDH;
#pragma unroll
        for (int i = 0; i < 4; ++i) {
            int c = tid + i * 256;
            int r = c >> 3, blk = c & 7;
            const uint32_t dst = s0 + r * QROWB + blk * 16;
            const int src = gk + r * NDH + blk * 8;
            cp_async16(dst,            kh + src);
            cp_async16(dst + KARR,     kl + src);
            cp_async16(dst + 2*KARR,   vh + src);
            cp_async16(dst + 3*KARR,   vl + src);
        }
        cp_commit();
    };

    load_kv(0, 0);
    __syncthreads();   // Q smem ready

    // Q fragments (held in registers for the whole kernel)
    uint32_t qfh[4][4], qfl[4][4];
    {
        const uint32_t qa = sb + (wid * 16 + (lane & 15)) * QROWB + (lane >> 4) * 16;
#pragma unroll
        for (int ks = 0; ks < 4; ++ks) {
            ldsm_x4(qa + ks * 32,        qfh[ks][0], qfh[ks][1], qfh[ks][2], qfh[ks][3]);
            ldsm_x4(qa + ks * 32 + KARR, qfl[ks][0], qfl[ks][1], qfl[ks][2], qfl[ks][3]);
        }
    }

    float m0r = -1e30f, m1r = -1e30f, lsum0 = 0.0f, lsum1 = 0.0f;
    float o[8][4];
#pragma unroll
    for (int di = 0; di < 8; ++di)
#pragma unroll
        for (int q = 0; q < 4; ++q) o[di][q] = 0.0f;

    for (int t = 0; t < ntiles; ++t) {
        const int stg = t & 1;
        if (t + 1 < ntiles) {
            load_kv(t + 1, stg ^ 1);
            asm volatile("cp.async.wait_group 1;" ::: "memory");
        } else {
            asm volatile("cp.async.wait_group 0;" ::: "memory");
        }
        __syncthreads();

        const uint32_t kbase = sb + 2 * KARR + stg * KVSTAGE;

        // ---- S = Q K^T ----
        float s[16][4];
#pragma unroll
        for (int ni = 0; ni < 16; ++ni)
#pragma unroll
            for (int q = 0; q < 4; ++q) s[ni][q] = 0.0f;

#pragma unroll
        for (int ks = 0; ks < 4; ++ks) {
#pragma unroll
            for (int nb = 0; nb < 8; ++nb) {
                const uint32_t adr = kbase
                    + (nb * 16 + (lane & 7) + 8 * (lane >> 4)) * QROWB
                    + ((lane >> 3) & 1) * 16 + ks * 32;
                uint32_t t0, t1, t2, t3, u0, u1, u2, u3;
                ldsm_x4(adr,        t0, t1, t2, t3);
                ldsm_x4(adr + KARR, u0, u1, u2, u3);
                uint32_t bh0[2] = {t0, t1}, bh1[2] = {t2, t3};
                uint32_t bl0[2] = {u0, u1}, bl1[2] = {u2, u3};
                mma16816(s[nb*2],   qfh[ks], bh0);
                mma16816(s[nb*2],   qfh[ks], bl0);
                mma16816(s[nb*2],   qfl[ks], bh0);
                mma16816(s[nb*2+1], qfh[ks], bh1);
                mma16816(s[nb*2+1], qfh[ks], bl1);
                mma16816(s[nb*2+1], qfl[ks], bh1);
            }
        }

        // ---- mask + online softmax (log2 domain) ----
        const int kv0 = t << 7;
        const int cb  = kv0 + 2 * (lane & 3);
        float tmax0 = -1e30f, tmax1 = -1e30f;
#pragma unroll
        for (int ni = 0; ni < 16; ++ni) {
            const int c0 = cb + 8 * ni;
            if (c0     >= len) { s[ni][0] = -1e30f; s[ni][2] = -1e30f; }
            if (c0 + 1 >= len) { s[ni][1] = -1e30f; s[ni][3] = -1e30f; }
            tmax0 = fmaxf(tmax0, fmaxf(s[ni][0], s[ni][1]));
            tmax1 = fmaxf(tmax1, fmaxf(s[ni][2], s[ni][3]));
        }
        tmax0 = fmaxf(tmax0, __shfl_xor_sync(0xffffffffu, tmax0, 1));
        tmax0 = fmaxf(tmax0, __shfl_xor_sync(0xffffffffu, tmax0, 2));
        tmax1 = fmaxf(tmax1, __shfl_xor_sync(0xffffffffu, tmax1, 1));
        tmax1 = fmaxf(tmax1, __shfl_xor_sync(0xffffffffu, tmax1, 2));

        const float mn0 = fmaxf(m0r, tmax0);
        const float mn1 = fmaxf(m1r, tmax1);
        const float sc0 = ex2(m0r - mn0);
        const float sc1 = ex2(m1r - mn1);
        m0r = mn0; m1r = mn1;

        float ps0 = 0.0f, ps1 = 0.0f;
        // p values packed hi/lo back into s[][] registers:
        // s[ni][0]=ph row r, s[ni][1]=pl row r, s[ni][2]=ph row r+8, s[ni][3]=pl row r+8
#pragma unroll
        for (int ni = 0; ni < 16; ++ni) {
            float p0 = ex2(s[ni][0] - mn0);
            float p1 = ex2(s[ni][1] - mn0);
            float p2 = ex2(s[ni][2] - mn1);
            float p3 = ex2(s[ni][3] - mn1);
            ps0 += p0 + p1;
            ps1 += p2 + p3;
            __nv_bfloat16 h0 = __float2bfloat16_rn(p0);
            __nv_bfloat16 h1 = __float2bfloat16_rn(p1);
            __nv_bfloat16 h2 = __float2bfloat16_rn(p2);
            __nv_bfloat16 h3 = __float2bfloat16_rn(p3);
            uint32_t phA = pack_bf2(__bfloat162float(h0), __bfloat162float(h1));
            uint32_t plA = pack_bf2(p0 - __bfloat162float(h0), p1 - __bfloat162float(h1));
            uint32_t phB = pack_bf2(__bfloat162float(h2), __bfloat162float(h3));
            uint32_t plB = pack_bf2(p2 - __bfloat162float(h2), p3 - __bfloat162float(h3));
            s[ni][0] = __uint_as_float(phA);
            s[ni][1] = __uint_as_float(plA);
            s[ni][2] = __uint_as_float(phB);
            s[ni][3] = __uint_as_float(plB);
        }
        ps0 += __shfl_xor_sync(0xffffffffu, ps0, 1);
        ps0 += __shfl_xor_sync(0xffffffffu, ps0, 2);
        ps1 += __shfl_xor_sync(0xffffffffu, ps1, 1);
        ps1 += __shfl_xor_sync(0xffffffffu, ps1, 2);
        lsum0 = lsum0 * sc0 + ps0;
        lsum1 = lsum1 * sc1 + ps1;
#pragma unroll
        for (int di = 0; di < 8; ++di) {
            o[di][0] *= sc0; o[di][1] *= sc0;
            o[di][2] *= sc1; o[di][3] *= sc1;
        }

        // ---- O += P V  (V natural [kv][d], B frags via ldmatrix.trans) ----
        const uint32_t vbase = kbase + 2 * KARR;
#pragma unroll
        for (int ks2 = 0; ks2 < 8; ++ks2) {
            uint32_t Ahf[4] = {
                __float_as_uint(s[2*ks2][0]),   __float_as_uint(s[2*ks2][2]),
                __float_as_uint(s[2*ks2+1][0]), __float_as_uint(s[2*ks2+1][2]) };
            uint32_t Alf[4] = {
                __float_as_uint(s[2*ks2][1]),   __float_as_uint(s[2*ks2][3]),
                __float_as_uint(s[2*ks2+1][1]), __float_as_uint(s[2*ks2+1][3]) };
#pragma unroll
            for (int db = 0; db < 4; ++db) {
                const uint32_t adr = vbase
                    + (ks2 * 16 + (lane & 7) + 8 * ((lane >> 3) & 1)) * QROWB
                    + ((lane >> 4) & 1) * 16 + db * 32;
                uint32_t t0, t1, t2, t3, u0, u1, u2, u3;
                ldsm_x4_t(adr,        t0, t1, t2, t3);
                ldsm_x4_t(adr + KARR, u0, u1, u2, u3);
                uint32_t vh0[2] = {t0, t1}, vh1[2] = {t2, t3};
                uint32_t vl0[2] = {u0, u1}, vl1[2] = {u2, u3};
                mma16816(o[db*2],   Ahf, vh0);
                mma16816(o[db*2],   Ahf, vl0);
                mma16816(o[db*2],   Alf, vh0);
                mma16816(o[db*2+1], Ahf, vh1);
                mma16816(o[db*2+1], Ahf, vl1);
                mma16816(o[db*2+1], Alf, vh1);
            }
        }
        __syncthreads();   // all warps done reading this stage
    }

    // ---- normalize + write ctx bf16 hi/lo [B,S,D] ----
    const float inv0 = 1.0f / lsum0;
    const float inv1 = 1.0f / lsum1;
    const int r  = lane >> 2;
    const int dc = 2 * (lane & 3);
    const int qrow0 = q0 + wid * 16 + r;
#pragma unroll
    for (int di = 0; di < 8; ++di) {
        const int d = 8 * di + dc;
        {
            const int idx = ((b * NS + qrow0) * ND) + h * NDH + d;
            float v0 = o[di][0] * inv0, v1 = o[di][1] * inv0;
            __nv_bfloat16 h0 = __float2bfloat16_rn(v0);
            __nv_bfloat16 h1 = __float2bfloat16_rn(v1);
            *(uint32_t*)&ch[idx] = pack_bf2(__bfloat162float(h0), __bfloat162float(h1));
            *(uint32_t*)&cl[idx] = pack_bf2(v0 - __bfloat162float(h0), v1 - __bfloat162float(h1));
        }
        {
            const int idx = ((b * NS + qrow0 + 8) * ND) + h * NDH + d;
            float v0 = o[di][2] * inv1, v1 = o[di][3] * inv1;
            __nv_bfloat16 h0 = __float2bfloat16_rn(v0);
            __nv_bfloat16 h1 = __float2bfloat16_rn(v1);
            *(uint32_t*)&ch[idx] = pack_bf2(__bfloat162float(h0), __bfloat162float(h1));
            *(uint32_t*)&cl[idx] = pack_bf2(v0 - __bfloat162float(h0), v1 - __bfloat162float(h1));
        }
    }
}

// ---------------------------------------------------------------------------
extern "C" void kernel_launch(void* const* d_in, const int* in_sizes, int n_in,
                              void* d_out, int out_size)
{
    (void)in_sizes; (void)n_in; (void)out_size;
    const float* Q  = (const float*)d_in[0];
    const float* K  = (const float*)d_in[1];
    const float* V  = (const float*)d_in[2];
    const float* Wq = (const float*)d_in[3];
    const float* bq = (const float*)d_in[4];
    const float* Wk = (const float*)d_in[5];
    const float* bk = (const float*)d_in[6];
    const float* Wv = (const float*)d_in[7];
    const float* bv = (const float*)d_in[8];
    const float* Wo = (const float*)d_in[9];
    const float* bo = (const float*)d_in[10];
    const void*  mk = d_in[11];
    float* out = (float*)d_out;

    __nv_bfloat16 *pqh, *pql, *pkh, *pkl, *pvh, *pvl, *pah, *pal, *pwh, *pwl;
    cudaGetSymbolAddress((void**)&pqh, g_qh);
    cudaGetSymbolAddress((void**)&pql, g_ql);
    cudaGetSymbolAddress((void**)&pkh, g_kh);
    cudaGetSymbolAddress((void**)&pkl, g_kl);
    cudaGetSymbolAddress((void**)&pvh, g_vh);
    cudaGetSymbolAddress((void**)&pvl, g_vl);
    cudaGetSymbolAddress((void**)&pah, g_ah);
    cudaGetSymbolAddress((void**)&pal, g_al);
    cudaGetSymbolAddress((void**)&pwh, g_wh);
    cudaGetSymbolAddress((void**)&pwl, g_wl);

    const int nx4 = (NB * NS * ND) / 4;
    const int nw4 = (ND * ND) / 4;

    cudaFuncSetAttribute(proj_hmma<1>, cudaFuncAttributeMaxDynamicSharedMemorySize, PROJ_SMEM);
    cudaFuncSetAttribute(proj_hmma<0>, cudaFuncAttributeMaxDynamicSharedMemorySize, PROJ_SMEM);
    cudaFuncSetAttribute(attn_hmma, cudaFuncAttributeMaxDynamicSharedMemorySize, ATTN_SMEM);

    dim3 gp(64, 4);
    const float QSCALE = 0.125f * 1.4426950408889634f;  // 1/sqrt(64) * log2(e)

    conv_kernel<<<(nw4 + 255) / 256, 256>>>(Wq, pwh, pwl, nw4);
    conv_kernel<<<(nx4 + 255) / 256, 256>>>(Q,  pah, pal, nx4);
    proj_hmma<1><<<gp, 256, PROJ_SMEM>>>(pah, pal, pwh, pwl, bq, nullptr, pqh, pql, QSCALE);

    conv_kernel<<<(nw4 + 255) / 256, 256>>>(Wk, pwh, pwl, nw4);
    conv_kernel<<<(nx4 + 255) / 256, 256>>>(K,  pah, pal, nx4);
    proj_hmma<1><<<gp, 256, PROJ_SMEM>>>(pah, pal, pwh, pwl, bk, nullptr, pkh, pkl, 1.0f);

    conv_kernel<<<(nw4 + 255) / 256, 256>>>(Wv, pwh, pwl, nw4);
    conv_kernel<<<(nx4 + 255) / 256, 256>>>(V,  pah, pal, nx4);
    proj_hmma<1><<<gp, 256, PROJ_SMEM>>>(pah, pal, pwh, pwl, bv, nullptr, pvh, pvl, 1.0f);

    attn_hmma<<<dim3(NS / 128, NB * NH), 256, ATTN_SMEM>>>(
        pqh, pql, pkh, pkl, pvh, pvl, pah, pal, mk);

    conv_kernel<<<(nw4 + 255) / 256, 256>>>(Wo, pwh, pwl, nw4);
    proj_hmma<0><<<gp, 256, PROJ_SMEM>>>(pah, pal, pwh, pwl, bo, out, nullptr, nullptr, 1.0f);
}